// round 17
// baseline (speedup 1.0000x reference)
#include <cuda_runtime.h>
#include <cuda_bf16.h>
#include <cstdint>
#include <math.h>

// ---------------------------------------------------------------------------
// Problem constants
//   B=2, H=W=256, C=192, HEADS=6, HEAD_DIM=32, WS=8, PW=4, HIDDEN=768
//   NTOK = B*H*W = 131072 tokens
// ---------------------------------------------------------------------------
#define NTOK   131072
#define QKVLD  288      // 192 (q) + 96 (kv) per token, bf16
#define HID    768
#define ATT_SCALE 0.17677669529663688f   // 32^-0.5

// Scratch (static device allocations — no cudaMalloc allowed)
__device__ __align__(16) __nv_bfloat16 g_xn  [(size_t)NTOK * 192]; // LN out
__device__ __align__(16) __nv_bfloat16 g_qkvb[(size_t)NTOK * QKVLD];
__device__ __align__(16) __nv_bfloat16 g_aw  [(size_t)NTOK * 192]; // attn out
__device__ __align__(16) float         g_x2  [(size_t)NTOK * 192]; // resid
__device__ __align__(16) __nv_bfloat16 g_h1  [(size_t)NTOK * HID]; // gelu(fc1)
__device__ __align__(16) __nv_bfloat16 g_h   [(size_t)NTOK * HID]; // ffn hidden
// bf16 weights: wqkv (192x288) | wproj | w1f | w2f
#define WB_WQKV  0
#define WB_WPROJ 55296
#define WB_W1F   92160
#define WB_W2F   239616
__device__ __align__(16) __nv_bfloat16 g_wb[387072];
__device__ __align__(16) float g_bqkv[288];

__device__ __forceinline__ float gelu_f(float v) {
    return 0.5f * v * (1.0f + erff(v * 0.70710678118654752440f));
}

// ---------------------------------------------------------------------------
// Weight/bias prep: concat wq|wkv into 192x288 + convert all weights to bf16
// ---------------------------------------------------------------------------
__global__ __launch_bounds__(256) void prep_kernel(
    const float* __restrict__ wq, const float* __restrict__ wkv,
    const float* __restrict__ wproj, const float* __restrict__ w1f,
    const float* __restrict__ w2f, __nv_bfloat16* __restrict__ wb,
    const float* __restrict__ bq, const float* __restrict__ bkv,
    float* __restrict__ bqkv)
{
    int i = blockIdx.x * 256 + threadIdx.x;
    if (i < 288) bqkv[i] = (i < 192) ? bq[i] : bkv[i - 192];
    if (i >= 387072) return;
    float v;
    if (i < 55296) {
        int row = i / 288, col = i - row * 288;
        v = (col < 192) ? wq[row * 192 + col] : wkv[row * 96 + col - 192];
    } else if (i < 92160) {
        v = wproj[i - 55296];
    } else if (i < 239616) {
        v = w1f[i - 92160];
    } else {
        v = w2f[i - 239616];
    }
    wb[i] = __float2bfloat16(v);
}

// ---------------------------------------------------------------------------
// LayerNorm (vectorized): one warp per TWO 192-wide rows, float4 loads,
// one-pass variance, uint2 (4x bf16) stores.
// ---------------------------------------------------------------------------
__global__ __launch_bounds__(256) void ln_kernel(
    const float* __restrict__ x, const float* __restrict__ g,
    const float* __restrict__ b, __nv_bfloat16* __restrict__ out)
{
    int wid  = blockIdx.x * 8 + (threadIdx.x >> 5);   // warp -> 2 rows
    int lane = threadIdx.x & 31;
    const float4* xp = (const float4*)(x + (size_t)wid * 384);
    float4 v[3];
    float s0 = 0.f, s1 = 0.f, q0 = 0.f, q1 = 0.f;
#pragma unroll
    for (int i = 0; i < 3; i++) {
        int f = lane + 32 * i;            // float4 index within row pair (0..95)
        float4 t = xp[f];
        v[i] = t;
        float sv = t.x + t.y + t.z + t.w;
        float qv = t.x*t.x + t.y*t.y + t.z*t.z + t.w*t.w;
        if (f < 48) { s0 += sv; q0 += qv; } else { s1 += sv; q1 += qv; }
    }
#pragma unroll
    for (int o = 16; o > 0; o >>= 1) {
        s0 += __shfl_xor_sync(0xffffffffu, s0, o);
        q0 += __shfl_xor_sync(0xffffffffu, q0, o);
        s1 += __shfl_xor_sync(0xffffffffu, s1, o);
        q1 += __shfl_xor_sync(0xffffffffu, q1, o);
    }
    float mu0 = s0 * (1.f/192.f), mu1 = s1 * (1.f/192.f);
    float iv0 = rsqrtf(q0 * (1.f/192.f) - mu0*mu0 + 1e-5f);
    float iv1 = rsqrtf(q1 * (1.f/192.f) - mu1*mu1 + 1e-5f);
    __nv_bfloat16* op = out + (size_t)wid * 384;
#pragma unroll
    for (int i = 0; i < 3; i++) {
        int f = lane + 32 * i;
        bool r1 = f >= 48;
        int col = (f - (r1 ? 48 : 0)) * 4;
        float mu = r1 ? mu1 : mu0, iv = r1 ? iv1 : iv0;
        float4 gv = *(const float4*)&g[col];
        float4 bv = *(const float4*)&b[col];
        float4 t = v[i];
        uint2 o2;
        *reinterpret_cast<__nv_bfloat162*>(&o2.x) = __float22bfloat162_rn(
            make_float2((t.x - mu) * iv * gv.x + bv.x,
                        (t.y - mu) * iv * gv.y + bv.y));
        *reinterpret_cast<__nv_bfloat162*>(&o2.y) = __float22bfloat162_rn(
            make_float2((t.z - mu) * iv * gv.z + bv.z,
                        (t.w - mu) * iv * gv.w + bv.w));
        *(uint2*)(op + (r1 ? 192 : 0) + col) = o2;
    }
}

// ---------------------------------------------------------------------------
// GEMM building blocks
// ---------------------------------------------------------------------------
__device__ __forceinline__ void cp16(uint32_t dst, const void* src, bool ok) {
    int sz = ok ? 16 : 0;
    asm volatile("cp.async.cg.shared.global [%0], [%1], 16, %2;\n"
                 :: "r"(dst), "l"(src), "r"(sz));
}
__device__ __forceinline__ void ldmx4(unsigned r[4], uint32_t addr) {
    asm volatile("ldmatrix.sync.aligned.m8n8.x4.shared.b16 {%0,%1,%2,%3}, [%4];"
                 : "=r"(r[0]), "=r"(r[1]), "=r"(r[2]), "=r"(r[3]) : "r"(addr));
}
__device__ __forceinline__ void ldmx4t(unsigned r[4], uint32_t addr) {
    asm volatile("ldmatrix.sync.aligned.m8n8.x4.trans.shared.b16 {%0,%1,%2,%3}, [%4];"
                 : "=r"(r[0]), "=r"(r[1]), "=r"(r[2]), "=r"(r[3]) : "r"(addr));
}
__device__ __forceinline__ void mma_bf16(float c[4], const unsigned a[4],
                                         unsigned b0, unsigned b1) {
    asm volatile(
        "mma.sync.aligned.m16n8k16.row.col.f32.bf16.bf16.f32 "
        "{%0,%1,%2,%3}, {%4,%5,%6,%7}, {%8,%9}, {%0,%1,%2,%3};"
        : "+f"(c[0]), "+f"(c[1]), "+f"(c[2]), "+f"(c[3])
        : "r"(a[0]), "r"(a[1]), "r"(a[2]), "r"(a[3]), "r"(b0), "r"(b1));
}

#define SA 40

// ---------------------------------------------------------------------------
// General bf16 GEMM (R14 config): BM=128, templated BN (64/128), BK=32,
// 256 threads = 8 warps (4m x 2n). 3-stage cp.async, modulo-3 unrolled,
// t+2 loads before the wait. K % 96 == 0.
// ---------------------------------------------------------------------------
template<int BN>
__global__ __launch_bounds__(256) void gemm_bf16_kernel(
    const __nv_bfloat16* __restrict__ A, int lda,
    const __nv_bfloat16* __restrict__ W, int ldw,
    const float* __restrict__ bias,
    void* __restrict__ Cc, int ldc,
    int N, int K,
    const float* __restrict__ res, int act, int out_bf16)
{
    constexpr int SBT = BN + 8;
    constexpr int NT  = BN / 16;
    constexpr int NP  = BN / 32;
    constexpr int BL  = BN / 64;
    constexpr int CPR = BN / 8;
    extern __shared__ __align__(16) __nv_bfloat16 smem[];
    __nv_bfloat16* Asm = smem;
    __nv_bfloat16* Bsm = smem + 3 * 128 * SA;
    int tid  = threadIdx.x;
    int lane = tid & 31;
    int warp = tid >> 5;
    int m0 = blockIdx.y * 128;
    int n0 = blockIdx.x * BN;
    int wm0 = (warp >> 1) * 32;
    int wn0 = (warp & 1) * (BN / 2);
    int g  = lane >> 2, cq = lane & 3;
    int ln15 = lane & 15, hi8 = (lane >> 4) << 3;

    uint32_t sAb[3], sBb[3];
#pragma unroll
    for (int s = 0; s < 3; s++) {
        sAb[s] = (uint32_t)__cvta_generic_to_shared(Asm + s * 128 * SA);
        sBb[s] = (uint32_t)__cvta_generic_to_shared(Bsm + s * 32 * SBT);
    }

    float acc[2][NT][4];
#pragma unroll
    for (int mt = 0; mt < 2; mt++)
#pragma unroll
        for (int nt = 0; nt < NT; nt++)
#pragma unroll
            for (int r = 0; r < 4; r++) acc[mt][nt][r] = 0.f;

    int a_r0 = tid >> 2, a_c = (tid & 3) << 3;
    int b_kr[BL], b_nq[BL]; bool b_okk[BL];
#pragma unroll
    for (int i = 0; i < BL; i++) {
        int ch = tid + i * 256;
        b_kr[i] = ch / CPR;
        b_nq[i] = (ch % CPR) * 8;
        b_okk[i] = (n0 + b_nq[i] + 8) <= N;
    }

    int T = K >> 5;
#define LOAD_TILE(slot, t_)                                                    \
    do {                                                                       \
        int kt_ = (t_) << 5;                                                   \
        cp16(sAb[slot] + (a_r0 * SA + a_c) * 2,                                \
             A + (size_t)(m0 + a_r0) * lda + kt_ + a_c, true);                 \
        cp16(sAb[slot] + ((a_r0 + 64) * SA + a_c) * 2,                         \
             A + (size_t)(m0 + a_r0 + 64) * lda + kt_ + a_c, true);            \
        _Pragma("unroll")                                                      \
        for (int i_ = 0; i_ < BL; i_++)                                        \
            cp16(sBb[slot] + (b_kr[i_] * SBT + b_nq[i_]) * 2,                  \
                 b_okk[i_] ? (const void*)(W + (size_t)(kt_ + b_kr[i_]) * ldw  \
                                           + n0 + b_nq[i_])                    \
                           : (const void*)W, b_okk[i_]);                       \
        asm volatile("cp.async.commit_group;\n");                              \
    } while (0)

#define COMPUTE(slot)                                                          \
    do {                                                                       \
        uint32_t ab = sAb[slot], bb = sBb[slot];                               \
        _Pragma("unroll")                                                      \
        for (int kb = 0; kb < 32; kb += 16) {                                  \
            unsigned af[2][4], bf[NP][4];                                      \
            _Pragma("unroll")                                                  \
            for (int mt = 0; mt < 2; mt++)                                     \
                ldmx4(af[mt], ab + ((wm0 + mt*16 + ln15) * SA + kb + hi8) * 2);\
            _Pragma("unroll")                                                  \
            for (int np = 0; np < NP; np++)                                    \
                ldmx4t(bf[np], bb + ((kb + ln15) * SBT + wn0 + np*16 + hi8) * 2);\
            _Pragma("unroll")                                                  \
            for (int mt = 0; mt < 2; mt++)                                     \
                _Pragma("unroll")                                              \
                for (int nt = 0; nt < NT; nt++)                                \
                    mma_bf16(acc[mt][nt], af[mt],                              \
                             bf[nt >> 1][(nt & 1) * 2],                        \
                             bf[nt >> 1][(nt & 1) * 2 + 1]);                   \
        }                                                                      \
    } while (0)

#define STEP(slot, nslot, t_)                                                  \
    do {                                                                       \
        __syncthreads();                                                       \
        if ((t_) + 2 < T) {                                                    \
            LOAD_TILE(nslot, (t_) + 2);                                        \
            asm volatile("cp.async.wait_group 2;\n");                          \
        } else if ((t_) + 1 < T) {                                             \
            asm volatile("cp.async.wait_group 1;\n");                          \
        } else {                                                               \
            asm volatile("cp.async.wait_group 0;\n");                          \
        }                                                                      \
        __syncthreads();                                                       \
        COMPUTE(slot);                                                         \
    } while (0)

    LOAD_TILE(0, 0);
    LOAD_TILE(1, 1);
    for (int t = 0; t < T; t += 3) {
        STEP(0, 2, t);
        STEP(1, 0, t + 1);
        STEP(2, 1, t + 2);
    }
#undef STEP
#undef COMPUTE
#undef LOAD_TILE

#pragma unroll
    for (int mt = 0; mt < 2; mt++) {
        int row0 = m0 + wm0 + mt * 16 + g;
#pragma unroll
        for (int nt = 0; nt < NT; nt++) {
            int col = n0 + wn0 + nt * 8 + cq * 2;
            if (col < N) {
                float b0 = bias[col], b1 = bias[col + 1];
#pragma unroll
                for (int hh = 0; hh < 2; hh++) {
                    int row = row0 + 8 * hh;
                    float v0 = acc[mt][nt][hh * 2 + 0] + b0;
                    float v1 = acc[mt][nt][hh * 2 + 1] + b1;
                    if (act) { v0 = gelu_f(v0); v1 = gelu_f(v1); }
                    if (res) {
                        float2 rr = *(const float2*)&res[(size_t)row * ldc + col];
                        v0 += rr.x; v1 += rr.y;
                    }
                    if (out_bf16) {
                        *(__nv_bfloat162*)&((__nv_bfloat16*)Cc)[(size_t)row * ldc + col] =
                            __float22bfloat162_rn(make_float2(v0, v1));
                    } else {
                        *(float2*)&((float*)Cc)[(size_t)row * ldc + col] =
                            make_float2(v0, v1);
                    }
                }
            }
        }
    }
}

// ---------------------------------------------------------------------------
// Fused proj GEMM + residual + LayerNorm2:
//   t = aw @ wproj + bproj + x ;  x2 = t ;  xn = LN(t) * g2 + be2
// BM=64, BN=192 (= full N, one CTA per row band), K=192, 128 threads =
// 4 warps (2m x 2n, warp tile 32x96). Epilogue stages t to smem for the
// per-row (N-dim) LN reduction.
// ---------------------------------------------------------------------------
#define PSB 200                       // B smem stride (192 + 8)
#define PROJ_SMEM (3 * (64 * SA + 32 * PSB) * 2)   // 53760 B

__global__ __launch_bounds__(128) void proj_ln_kernel(
    const __nv_bfloat16* __restrict__ A,      // aw, lda 192
    const __nv_bfloat16* __restrict__ W,      // wproj 192x192 bf16
    const float* __restrict__ bias,           // bproj
    const float* __restrict__ resid,          // x  (fp32)
    const float* __restrict__ g2, const float* __restrict__ be2,
    float* __restrict__ x2, __nv_bfloat16* __restrict__ xn)
{
    extern __shared__ __align__(16) __nv_bfloat16 smem[];
    __nv_bfloat16* Asm = smem;                  // 3 x 64*SA
    __nv_bfloat16* Bsm = smem + 3 * 64 * SA;    // 3 x 32*PSB
    __shared__ float gs[192], bs2[192];
    int tid  = threadIdx.x;
    int lane = tid & 31;
    int warp = tid >> 5;
    int m0 = blockIdx.x * 64;
    int wm0 = (warp >> 1) * 32;
    int wn0 = (warp & 1) * 96;
    int g  = lane >> 2, cq = lane & 3;
    int ln15 = lane & 15, hi8 = (lane >> 4) << 3;

    for (int i = tid; i < 192; i += 128) { gs[i] = g2[i]; bs2[i] = be2[i]; }

    uint32_t sAb[3], sBb[3];
#pragma unroll
    for (int s = 0; s < 3; s++) {
        sAb[s] = (uint32_t)__cvta_generic_to_shared(Asm + s * 64 * SA);
        sBb[s] = (uint32_t)__cvta_generic_to_shared(Bsm + s * 32 * PSB);
    }

    float acc[2][12][4];
#pragma unroll
    for (int mt = 0; mt < 2; mt++)
#pragma unroll
        for (int nt = 0; nt < 12; nt++)
#pragma unroll
            for (int r = 0; r < 4; r++) acc[mt][nt][r] = 0.f;

    // Loaders: A 64x32 = 256 chunks -> 2/thread; B 32x192 = 768 -> 6/thread.
    int a_r0 = tid >> 2, a_c = (tid & 3) << 3;
    int b_kr[6], b_nq[6];
#pragma unroll
    for (int i = 0; i < 6; i++) {
        int ch = tid + i * 128;
        b_kr[i] = ch / 24;
        b_nq[i] = (ch % 24) * 8;
    }

    const int T = 6;
#define LOAD_TILE(slot, t_)                                                    \
    do {                                                                       \
        int kt_ = (t_) << 5;                                                   \
        cp16(sAb[slot] + (a_r0 * SA + a_c) * 2,                                \
             A + (size_t)(m0 + a_r0) * 192 + kt_ + a_c, true);                 \
        cp16(sAb[slot] + ((a_r0 + 32) * SA + a_c) * 2,                         \
             A + (size_t)(m0 + a_r0 + 32) * 192 + kt_ + a_c, true);            \
        _Pragma("unroll")                                                      \
        for (int i_ = 0; i_ < 6; i_++)                                         \
            cp16(sBb[slot] + (b_kr[i_] * PSB + b_nq[i_]) * 2,                  \
                 W + (size_t)(kt_ + b_kr[i_]) * 192 + b_nq[i_], true);         \
        asm volatile("cp.async.commit_group;\n");                              \
    } while (0)

#define COMPUTE(slot)                                                          \
    do {                                                                       \
        uint32_t ab = sAb[slot], bb = sBb[slot];                               \
        _Pragma("unroll")                                                      \
        for (int kb = 0; kb < 32; kb += 16) {                                  \
            unsigned af[2][4], bf[6][4];                                       \
            _Pragma("unroll")                                                  \
            for (int mt = 0; mt < 2; mt++)                                     \
                ldmx4(af[mt], ab + ((wm0 + mt*16 + ln15) * SA + kb + hi8) * 2);\
            _Pragma("unroll")                                                  \
            for (int np = 0; np < 6; np++)                                     \
                ldmx4t(bf[np], bb + ((kb + ln15) * PSB + wn0 + np*16 + hi8) * 2);\
            _Pragma("unroll")                                                  \
            for (int mt = 0; mt < 2; mt++)                                     \
                _Pragma("unroll")                                              \
                for (int nt = 0; nt < 12; nt++)                                \
                    mma_bf16(acc[mt][nt], af[mt],                              \
                             bf[nt >> 1][(nt & 1) * 2],                        \
                             bf[nt >> 1][(nt & 1) * 2 + 1]);                   \
        }                                                                      \
    } while (0)

#define STEP(slot, nslot, t_)                                                  \
    do {                                                                       \
        __syncthreads();                                                       \
        if ((t_) + 2 < T) {                                                    \
            LOAD_TILE(nslot, (t_) + 2);                                        \
            asm volatile("cp.async.wait_group 2;\n");                          \
        } else if ((t_) + 1 < T) {                                             \
            asm volatile("cp.async.wait_group 1;\n");                          \
        } else {                                                               \
            asm volatile("cp.async.wait_group 0;\n");                          \
        }                                                                      \
        __syncthreads();                                                       \
        COMPUTE(slot);                                                         \
    } while (0)

    LOAD_TILE(0, 0);
    LOAD_TILE(1, 1);
    STEP(0, 2, 0);
    STEP(1, 0, 1);
    STEP(2, 1, 2);
    STEP(0, 2, 3);
    STEP(1, 0, 4);
    STEP(2, 1, 5);
#undef STEP
#undef COMPUTE
#undef LOAD_TILE

    // ---- epilogue phase 1: t = acc + bias + resid; write x2; stage t ----
    __syncthreads();                       // all COMPUTE smem reads done
    float* ep = (float*)smem;              // 64 x 196 fp32 = 50176 B
#pragma unroll
    for (int mt = 0; mt < 2; mt++) {
        int lr0 = wm0 + mt * 16 + g;
#pragma unroll
        for (int nt = 0; nt < 12; nt++) {
            int col = wn0 + nt * 8 + cq * 2;
            float b0 = bias[col], b1 = bias[col + 1];
#pragma unroll
            for (int hh = 0; hh < 2; hh++) {
                int lr = lr0 + 8 * hh;
                int row = m0 + lr;
                float2 rr = *(const float2*)&resid[(size_t)row * 192 + col];
                float v0 = acc[mt][nt][hh * 2 + 0] + b0 + rr.x;
                float v1 = acc[mt][nt][hh * 2 + 1] + b1 + rr.y;
                *(float2*)&x2[(size_t)row * 192 + col] = make_float2(v0, v1);
                ep[lr * 196 + col]     = v0;
                ep[lr * 196 + col + 1] = v1;
            }
        }
    }
    __syncthreads();

    // ---- epilogue phase 2: per-row LN over 192 cols; write xn (bf16) ----
    for (int r = warp * 16; r < warp * 16 + 16; r++) {
        float v[6];
        float s = 0.f, q = 0.f;
#pragma unroll
        for (int i = 0; i < 6; i++) {
            v[i] = ep[r * 196 + lane + 32 * i];
            s += v[i]; q += v[i] * v[i];
        }
#pragma unroll
        for (int o = 16; o > 0; o >>= 1) {
            s += __shfl_xor_sync(0xffffffffu, s, o);
            q += __shfl_xor_sync(0xffffffffu, q, o);
        }
        float mu = s * (1.f/192.f);
        float iv = rsqrtf(q * (1.f/192.f) - mu*mu + 1e-5f);
        __nv_bfloat16* op = xn + (size_t)(m0 + r) * 192;
#pragma unroll
        for (int i = 0; i < 6; i++) {
            int c = lane + 32 * i;
            op[c] = __float2bfloat16((v[i] - mu) * iv * gs[c] + bs2[c]);
        }
    }
}

// ---------------------------------------------------------------------------
// Windowed PSA attention.  One block per 8x8 window (2048 windows).
// ---------------------------------------------------------------------------
__global__ __launch_bounds__(384) void attn_kernel(
    const __nv_bfloat16* __restrict__ qkv,
    const float* __restrict__ bias_table,
    __nv_bfloat16* __restrict__ aw)
{
    __shared__ float ks[16][192];
    __shared__ float vs[16][192];
    __shared__ float bt[296];
    int w  = blockIdx.x;
    int b  = w >> 10;
    int wi = w & 1023;
    int wy = wi >> 5, wx = wi & 31;
    int gbase = b*65536 + wy*2048 + wx*8;
    int tid = threadIdx.x;

    for (int i = tid; i < 294; i += 384) bt[i] = bias_table[i];
    {
        int kt = tid / 24;
        int f0 = (tid - kt * 24) * 8;
        int s0 = f0 / 96;
        int s1 = (f0 / 48) & 1;
        int c  = f0 % 48;
        int p0 = kt >> 2, p1 = kt & 3;
        int g  = gbase + (p0*2 + s0)*256 + (p1*2 + s1);
        const __nv_bfloat16* row = qkv + (size_t)g*QKVLD + 192;
        uint4 kraw = *(const uint4*)(row + c);
        uint4 vraw = *(const uint4*)(row + 48 + c);
        const __nv_bfloat162* kp = (const __nv_bfloat162*)&kraw;
        const __nv_bfloat162* vp = (const __nv_bfloat162*)&vraw;
        float2 t0 = __bfloat1622float2(kp[0]), t1 = __bfloat1622float2(kp[1]);
        float2 t2 = __bfloat1622float2(kp[2]), t3 = __bfloat1622float2(kp[3]);
        *(float4*)&ks[kt][f0]     = make_float4(t0.x, t0.y, t1.x, t1.y);
        *(float4*)&ks[kt][f0 + 4] = make_float4(t2.x, t2.y, t3.x, t3.y);
        t0 = __bfloat1622float2(vp[0]); t1 = __bfloat1622float2(vp[1]);
        t2 = __bfloat1622float2(vp[2]); t3 = __bfloat1622float2(vp[3]);
        *(float4*)&vs[kt][f0]     = make_float4(t0.x, t0.y, t1.x, t1.y);
        *(float4*)&vs[kt][f0 + 4] = make_float4(t2.x, t2.y, t3.x, t3.y);
    }
    __syncthreads();

    int h  = tid / 64;
    int qt = tid - h*64;
    int qi = qt >> 3, qj = qt & 7;
    int g  = gbase + qi*256 + qj;
    const __nv_bfloat16* qp = qkv + (size_t)g*QKVLD + h*32;
    float4 q4[8];
#pragma unroll
    for (int d = 0; d < 4; d++) {
        uint4 raw = *(const uint4*)(qp + d*8);
        const __nv_bfloat162* p2 = (const __nv_bfloat162*)&raw;
        float2 a0 = __bfloat1622float2(p2[0]);
        float2 a1 = __bfloat1622float2(p2[1]);
        float2 a2 = __bfloat1622float2(p2[2]);
        float2 a3 = __bfloat1622float2(p2[3]);
        q4[d*2]   = make_float4(a0.x*ATT_SCALE, a0.y*ATT_SCALE,
                                a1.x*ATT_SCALE, a1.y*ATT_SCALE);
        q4[d*2+1] = make_float4(a2.x*ATT_SCALE, a2.y*ATT_SCALE,
                                a3.x*ATT_SCALE, a3.y*ATT_SCALE);
    }
    float sc[16]; float mx = -1e30f;
    int rq0 = (qi >> 1) + 3, rq1 = (qj >> 1) + 3;
#pragma unroll
    for (int kt = 0; kt < 16; kt++) {
        const float4* kr = (const float4*)&ks[kt][h*32];
        float s = 0.f;
#pragma unroll
        for (int j = 0; j < 8; j++) {
            float4 kv4 = kr[j];
            s += q4[j].x*kv4.x + q4[j].y*kv4.y + q4[j].z*kv4.z + q4[j].w*kv4.w;
        }
        int rel = (rq0 - (kt >> 2))*7 + rq1 - (kt & 3);
        s += bt[rel*6 + h];
        sc[kt] = s;
        mx = fmaxf(mx, s);
    }
    float sum = 0.f;
#pragma unroll
    for (int kt = 0; kt < 16; kt++) { sc[kt] = __expf(sc[kt] - mx); sum += sc[kt]; }
    float inv = 1.f / sum;
    float4 o4[8];
#pragma unroll
    for (int j = 0; j < 8; j++) o4[j] = make_float4(0.f, 0.f, 0.f, 0.f);
#pragma unroll
    for (int kt = 0; kt < 16; kt++) {
        float a = sc[kt]*inv;
        const float4* vr = (const float4*)&vs[kt][h*32];
#pragma unroll
        for (int j = 0; j < 8; j++) {
            float4 vv = vr[j];
            o4[j].x += a*vv.x; o4[j].y += a*vv.y;
            o4[j].z += a*vv.z; o4[j].w += a*vv.w;
        }
    }
    __nv_bfloat16* op = aw + (size_t)g*192 + h*32;
#pragma unroll
    for (int j = 0; j < 4; j++) {
        uint4 o;
        __nv_bfloat162* o2 = (__nv_bfloat162*)&o;
        o2[0] = __float22bfloat162_rn(make_float2(o4[j*2].x,   o4[j*2].y));
        o2[1] = __float22bfloat162_rn(make_float2(o4[j*2].z,   o4[j*2].w));
        o2[2] = __float22bfloat162_rn(make_float2(o4[j*2+1].x, o4[j*2+1].y));
        o2[3] = __float22bfloat162_rn(make_float2(o4[j*2+1].z, o4[j*2+1].w));
        *(uint4*)(op + j*8) = o;
    }
}

// ---------------------------------------------------------------------------
// Depthwise 5x5 conv + GELU + residual:  out = h1 + gelu(conv(h1) + dwb)
// 4 x-adjacent tokens x 8 channels per thread (5x8 shared window).
// ---------------------------------------------------------------------------
__global__ __launch_bounds__(256) void dwconv_kernel(
    const __nv_bfloat16* __restrict__ h1, const float* __restrict__ wk,
    const float* __restrict__ wb, __nv_bfloat16* __restrict__ out)
{
    __shared__ __align__(16) uint32_t ws2[25][64];
    __shared__ float bs[128];
    int cb  = blockIdx.y * 128;
    int tid = threadIdx.x;
    for (int i = tid; i < 1600; i += 256) {
        int k = i >> 6, pp = i & 63;
        __nv_bfloat162 pk = __floats2bfloat162_rn(
            wk[(size_t)(cb + 2*pp)     * 25 + k],
            wk[(size_t)(cb + 2*pp + 1) * 25 + k]);
        ws2[k][pp] = *reinterpret_cast<uint32_t*>(&pk);
    }
    if (tid < 128) bs[tid] = wb[cb + tid];
    __syncthreads();

    int grp = tid >> 4;
    int oc  = tid & 15;
    int token0 = blockIdx.x * 64 + grp * 4;
    int b = token0 >> 16;
    int p = token0 & 65535;
    int y = p >> 8, x0 = p & 255;
    int ch = cb + oc * 8;
    const size_t rowbase = (size_t)(b * 65536 + y * 256);

    __nv_bfloat162 z = __float2bfloat162_rn(0.f);
    __nv_bfloat162 acc[4][4];
#pragma unroll
    for (int tk = 0; tk < 4; tk++)
#pragma unroll
        for (int j = 0; j < 4; j++) acc[tk][j] = z;
    uint4 cen[4];
#pragma unroll
    for (int tk = 0; tk < 4; tk++) cen[tk] = make_uint4(0u,0u,0u,0u);

#pragma unroll
    for (int dy = 0; dy < 5; dy++) {
        int yy = y + dy - 2;
        bool yok = (unsigned)yy < 256u;
        size_t rb = (size_t)(b * 65536 + yy * 256);
        uint4 col[8];
#pragma unroll
        for (int jx = 0; jx < 8; jx++) {
            int xc = x0 + jx - 2;
            uint4 v = make_uint4(0u, 0u, 0u, 0u);
            if (yok && (unsigned)xc < 256u)
                v = *(const uint4*)&h1[(rb + xc) * HID + ch];
            col[jx] = v;
        }
        if (dy == 2) {
#pragma unroll
            for (int tk = 0; tk < 4; tk++) cen[tk] = col[tk + 2];
        }
#pragma unroll
        for (int jx = 0; jx < 8; jx++) {
            const __nv_bfloat162* vp = reinterpret_cast<const __nv_bfloat162*>(&col[jx]);
#pragma unroll
            for (int tk = 0; tk < 4; tk++) {
                int tap = jx - tk;
                if (tap >= 0 && tap < 5) {
                    uint4 wv = *(const uint4*)&ws2[dy*5 + tap][oc*4];
                    const __nv_bfloat162* wp =
                        reinterpret_cast<const __nv_bfloat162*>(&wv);
#pragma unroll
                    for (int j = 0; j < 4; j++)
                        acc[tk][j] = __hfma2(vp[j], wp[j], acc[tk][j]);
                }
            }
        }
    }

#pragma unroll
    for (int tk = 0; tk < 4; tk++) {
        const __nv_bfloat162* cp = reinterpret_cast<const __nv_bfloat162*>(&cen[tk]);
        uint4 o;
        __nv_bfloat162* op2 = reinterpret_cast<__nv_bfloat162*>(&o);
#pragma unroll
        for (int j = 0; j < 4; j++) {
            float b0 = bs[oc*8 + 2*j], b1 = bs[oc*8 + 2*j + 1];
            float2 a = __bfloat1622float2(acc[tk][j]);
            float2 c = __bfloat1622float2(cp[j]);
            op2[j] = __float22bfloat162_rn(make_float2(c.x + gelu_f(a.x + b0),
                                                       c.y + gelu_f(a.y + b1)));
        }
        *(uint4*)&out[(rowbase + x0 + tk) * HID + ch] = o;
    }
}

// ---------------------------------------------------------------------------
// Launch sequence (graph-capturable: kernel launches only)
// ---------------------------------------------------------------------------
extern "C" void kernel_launch(void* const* d_in, const int* in_sizes, int n_in,
                              void* d_out, int out_size)
{
    const float* x    = (const float*)d_in[0];
    const float* g1   = (const float*)d_in[1];
    const float* be1  = (const float*)d_in[2];
    const float* wq   = (const float*)d_in[3];
    const float* bq   = (const float*)d_in[4];
    const float* wkv  = (const float*)d_in[5];
    const float* bkv  = (const float*)d_in[6];
    const float* btab = (const float*)d_in[7];
    const float* wproj= (const float*)d_in[8];
    const float* bproj= (const float*)d_in[9];
    const float* g2   = (const float*)d_in[10];
    const float* be2  = (const float*)d_in[11];
    const float* w1f  = (const float*)d_in[12];
    const float* b1f  = (const float*)d_in[13];
    const float* dwk  = (const float*)d_in[14];
    const float* dwb  = (const float*)d_in[15];
    const float* w2f  = (const float*)d_in[16];
    const float* b2f  = (const float*)d_in[17];
    float* out = (float*)d_out;

    __nv_bfloat16 *xn, *qkvb, *aw, *h1, *h, *wb;
    float *x2, *bqkv;
    cudaGetSymbolAddress((void**)&xn,   g_xn);
    cudaGetSymbolAddress((void**)&qkvb, g_qkvb);
    cudaGetSymbolAddress((void**)&aw,   g_aw);
    cudaGetSymbolAddress((void**)&x2,   g_x2);
    cudaGetSymbolAddress((void**)&h1,   g_h1);
    cudaGetSymbolAddress((void**)&h,    g_h);
    cudaGetSymbolAddress((void**)&wb,   g_wb);
    cudaGetSymbolAddress((void**)&bqkv, g_bqkv);

    const int smem64  = 3 * (128 * SA + 32 * 72)  * 2;   // 44544 B
    const int smem128 = 3 * (128 * SA + 32 * 136) * 2;   // 56832 B
    cudaFuncSetAttribute(gemm_bf16_kernel<128>,
                         cudaFuncAttributeMaxDynamicSharedMemorySize, smem128);
    cudaFuncSetAttribute(proj_ln_kernel,
                         cudaFuncAttributeMaxDynamicSharedMemorySize, PROJ_SMEM);

    // 0. Weight/bias prep (bf16, QKV concat)
    prep_kernel<<<(387072 + 255)/256, 256>>>(wq, wkv, wproj, w1f, w2f, wb,
                                             bq, bkv, bqkv);

    // 1. LN1 -> xn (bf16)
    ln_kernel<<<NTOK/16, 256>>>(x, g1, be1, xn);
    // 2. QKV = xn @ wqkv + bqkv  (bf16, ldc=288; BN=128 -> 3 n-blocks)
    gemm_bf16_kernel<128><<<dim3(3, NTOK/128), 256, smem128>>>(
        xn, 192, wb + WB_WQKV, 288, bqkv, qkvb, QKVLD, 288, 192, nullptr, 0, 1);
    // 3. Window attention -> aw (bf16, token order)
    attn_kernel<<<2048, 384>>>(qkvb, btab, aw);
    // 4+5. Fused: x2 = aw @ wproj + bproj + x ; xn = LN2(x2)
    proj_ln_kernel<<<NTOK/64, 128, PROJ_SMEM>>>(
        aw, wb + WB_WPROJ, bproj, x, g2, be2, x2, xn);
    // 6. h1 = gelu(xn @ w1f + b1f)  (bf16; BN=128 -> 6 n-blocks)
    gemm_bf16_kernel<128><<<dim3(6, NTOK/128), 256, smem128>>>(
        xn, 192, wb + WB_W1F, HID, b1f, h1, HID, HID, 192, nullptr, 1, 1);
    // 7. h = h1 + gelu(dwconv(h1) + dwb)  (bf16, 4 tokens/thread)
    dwconv_kernel<<<dim3(NTOK/64, 6), 256>>>(h1, dwk, dwb, h);
    // 8. out = h @ w2f + b2f + x2  (fp32; BN=64 -> 3 n-blocks)
    gemm_bf16_kernel<64><<<dim3(3, NTOK/128), 256, smem64>>>(
        h, HID, wb + WB_W2F, 192, b2f, out, 192, 192, HID, x2, 0, 0);
}